// round 16
// baseline (speedup 1.0000x reference)
#include <cuda_runtime.h>
#include <cuda_fp16.h>
#include <cstdint>

// ---------------------------------------------------------------------------
// MedianConvolution: out[n,c] = lower_median_k( (x @ W^T)[nbrs[n,k], c] )
// N=100000, K=32, IN_C=128, OUT_C=64.  nbrs is int32 (JAX demotes int64).
// GEMM: tensor cores with error-compensated fp16 split (hi/lo, 3 MMAs):
//   x@W ~= xh@Wh + xh@Wl + xl@Wh  -> fp32-accurate h, then fp16 store.
// Median: packed half2 Batcher network (78.4us measured, protected).
// ---------------------------------------------------------------------------

#define N_NODES 100000
#define IN_C    128
#define OUT_C   64
#define KNBR    32

#define BM 128              // rows per block (8 warps x 16 rows)
#define XS 65               // row stride in u32 words (130 halves = 260B)

// dynamic smem layout (offsets in halves; all 16B-aligned)
#define XA_HALVES   (BM * 2 * XS)        // 16640 halves = 33.3 KB
#define WB_HALVES   (OUT_C * 2 * XS)     //  8320 halves = 16.6 KB
#define OFF_XHI     0
#define OFF_XLO     (XA_HALVES)
#define OFF_WHI     (2 * XA_HALVES)
#define OFF_WLO     (2 * XA_HALVES + WB_HALVES)
#define SMEM_BYTES  ((2 * XA_HALVES + 2 * WB_HALVES) * 2)   // 99840 B

// intermediate h = x @ W^T in fp16 (12.8 MB static scratch — allocation-free)
__device__ __align__(16) __half g_h[N_NODES * OUT_C];

__device__ __forceinline__ unsigned h2u(__half2 p) {
    return *reinterpret_cast<unsigned*>(&p);
}

// split a float pair into fp16 hi and fp16 residual lo (packed words)
__device__ __forceinline__ void split2(float a, float b,
                                       unsigned& hi, unsigned& lo) {
    __half2 h = __floats2half2_rn(a, b);
    float2 hf = __half22float2(h);
    __half2 l = __floats2half2_rn(a - hf.x, b - hf.y);
    hi = h2u(h);
    lo = h2u(l);
}

#define MMA(c0_,c1_,c2_,c3_,a0_,a1_,a2_,a3_,b0_,b1_)                        \
    asm volatile(                                                            \
        "mma.sync.aligned.m16n8k16.row.col.f32.f16.f16.f32 "                 \
        "{%0,%1,%2,%3}, {%4,%5,%6,%7}, {%8,%9}, {%0,%1,%2,%3};"              \
        : "+f"(c0_), "+f"(c1_), "+f"(c2_), "+f"(c3_)                         \
        : "r"(a0_), "r"(a1_), "r"(a2_), "r"(a3_), "r"(b0_), "r"(b1_))

// ---------------------------------------------------------------------------
// Kernel 1: h = x @ W^T via split-fp16 HMMA (fragment mapping proven in R14).
// ---------------------------------------------------------------------------
__global__ __launch_bounds__(256) void gemm_kernel(
    const float* __restrict__ x,
    const float* __restrict__ W,
    int n)
{
    extern __shared__ __align__(16) __half smem[];
    unsigned* xhi = reinterpret_cast<unsigned*>(smem + OFF_XHI);
    unsigned* xlo = reinterpret_cast<unsigned*>(smem + OFF_XLO);
    unsigned* whi = reinterpret_cast<unsigned*>(smem + OFF_WHI);
    unsigned* wlo = reinterpret_cast<unsigned*>(smem + OFF_WLO);

    const int tid = threadIdx.x;
    const int rowBase = blockIdx.x * BM;

    // stage W -> fp16 hi/lo, native [n][k] layout (k contiguous)
    for (int e = tid; e < OUT_C * IN_C / 4; e += 256) {   // 2048 float4
        float4 v = __ldg(reinterpret_cast<const float4*>(W) + e);
        int c = e >> 5, k4 = e & 31;
        unsigned h0, l0, h1, l1;
        split2(v.x, v.y, h0, l0);
        split2(v.z, v.w, h1, l1);
        whi[c * XS + k4 * 2 + 0] = h0;
        whi[c * XS + k4 * 2 + 1] = h1;
        wlo[c * XS + k4 * 2 + 0] = l0;
        wlo[c * XS + k4 * 2 + 1] = l1;
    }

    // stage x -> fp16 hi/lo: 128 rows x 128 k = 4096 float4, 16 per thread
#pragma unroll
    for (int i = 0; i < 16; i++) {
        int e   = tid + i * 256;          // 0..4095
        int row = e >> 5;                 // 0..127
        int q   = e & 31;                 // float4 within row
        int grow = rowBase + row;
        float4 v = make_float4(0.f, 0.f, 0.f, 0.f);
        if (grow < n)
            v = __ldg(reinterpret_cast<const float4*>(
                    x + (size_t)grow * IN_C) + q);
        unsigned h0, l0, h1, l1;
        split2(v.x, v.y, h0, l0);
        split2(v.z, v.w, h1, l1);
        xhi[row * XS + q * 2 + 0] = h0;
        xhi[row * XS + q * 2 + 1] = h1;
        xlo[row * XS + q * 2 + 0] = l0;
        xlo[row * XS + q * 2 + 1] = l1;
    }
    __syncthreads();

    const int w    = tid >> 5;            // warp 0..7 -> rows 16w..16w+15
    const int lane = tid & 31;
    const int g    = lane >> 2;           // group id 0..7
    const int t    = lane & 3;            // thread-in-group 0..3

    float c0[8], c1[8], c2[8], c3[8];
#pragma unroll
    for (int nt = 0; nt < 8; nt++) { c0[nt]=0.f; c1[nt]=0.f; c2[nt]=0.f; c3[nt]=0.f; }

    const int rA  = (w * 16 + g) * XS;
    const int rA8 = rA + 8 * XS;

#pragma unroll
    for (int ks = 0; ks < 8; ks++) {      // K chunks of 16
        const int kw = ks * 8 + t;
        const unsigned ah0 = xhi[rA  + kw];
        const unsigned ah1 = xhi[rA8 + kw];
        const unsigned ah2 = xhi[rA  + kw + 4];
        const unsigned ah3 = xhi[rA8 + kw + 4];
        const unsigned al0 = xlo[rA  + kw];
        const unsigned al1 = xlo[rA8 + kw];
        const unsigned al2 = xlo[rA  + kw + 4];
        const unsigned al3 = xlo[rA8 + kw + 4];

#pragma unroll
        for (int nt = 0; nt < 8; nt++) {
            const int nb = (nt * 8 + g) * XS + kw;
            const unsigned bh0 = whi[nb];
            const unsigned bh1 = whi[nb + 4];
            const unsigned bl0 = wlo[nb];
            const unsigned bl1 = wlo[nb + 4];
            MMA(c0[nt], c1[nt], c2[nt], c3[nt], ah0, ah1, ah2, ah3, bh0, bh1);
            MMA(c0[nt], c1[nt], c2[nt], c3[nt], ah0, ah1, ah2, ah3, bl0, bl1);
            MMA(c0[nt], c1[nt], c2[nt], c3[nt], al0, al1, al2, al3, bh0, bh1);
        }
    }

    // epilogue: c0/c1 -> row g, cols (nt*8+2t, +1); c2/c3 -> row g+8
    const int row0 = rowBase + w * 16 + g;
    const int row8 = row0 + 8;
#pragma unroll
    for (int nt = 0; nt < 8; nt++) {
        const int col = nt * 8 + t * 2;
        if (row0 < n) {
            __half2 p = __floats2half2_rn(c0[nt], c1[nt]);
            *reinterpret_cast<__half2*>(g_h + (size_t)row0 * OUT_C + col) = p;
        }
        if (row8 < n) {
            __half2 p = __floats2half2_rn(c2[nt], c3[nt]);
            *reinterpret_cast<__half2*>(g_h + (size_t)row8 * OUT_C + col) = p;
        }
    }
}

// ---------------------------------------------------------------------------
// Kernel 2: gather + lower-median over K=32, packed half2 (2 channels/thread).
// 256 threads/block = 8 nodes x 32 threads; warp = 32 channel-pairs of one
// node -> each neighbor gather is exactly one 128B line (L2-resident).
// Median: explicit Batcher odd-even mergesort (63 comparators) per half,
// then 16th-smallest of the merge via max_i min(A[i], B[15-i]).
// Measured 78.4us, alu-bound.  DO NOT TOUCH.
// ---------------------------------------------------------------------------
__device__ __forceinline__ void cas2(__half2& a, __half2& b) {
    __half2 lo = __hmin2(a, b);
    b = __hmax2(a, b);
    a = lo;
}

#define S(i,j) cas2(v[i], v[j])
__device__ __forceinline__ void bsort16h(__half2* v) {
    // L1
    S(0,1); S(2,3); S(4,5); S(6,7); S(8,9); S(10,11); S(12,13); S(14,15);
    // L2
    S(0,2); S(1,3); S(4,6); S(5,7); S(8,10); S(9,11); S(12,14); S(13,15);
    // L3
    S(1,2); S(5,6); S(9,10); S(13,14);
    // L4
    S(0,4); S(1,5); S(2,6); S(3,7); S(8,12); S(9,13); S(10,14); S(11,15);
    // L5
    S(2,4); S(3,5); S(10,12); S(11,13);
    // L6
    S(1,2); S(3,4); S(5,6); S(9,10); S(11,12); S(13,14);
    // L7
    S(0,8); S(1,9); S(2,10); S(3,11); S(4,12); S(5,13); S(6,14); S(7,15);
    // L8
    S(4,8); S(5,9); S(6,10); S(7,11);
    // L9
    S(2,4); S(3,5); S(6,8); S(7,9); S(10,12); S(11,13);
    // L10
    S(1,2); S(3,4); S(5,6); S(7,8); S(9,10); S(11,12); S(13,14);
}
#undef S

__global__ __launch_bounds__(256) void median_kernel(
    const int* __restrict__ nbrs,      // int32
    float* __restrict__ out,
    int n)
{
    __shared__ int snb[8 * KNBR];

    const int base = blockIdx.x * 8;
    const int tid = threadIdx.x;

    {
        int node = base + (tid >> 5);
        int idx = (node < n) ? nbrs[(size_t)node * KNBR + (tid & 31)] : 0;
        idx = max(0, min(idx, n - 1));   // defensive clamp
        snb[tid] = idx;
    }
    __syncthreads();

    const int ty = tid >> 5;   // node within block (0..7)
    const int tx = tid & 31;   // channel-pair index (channels 2tx, 2tx+1)
    const int node = base + ty;
    if (node >= n) return;

    const __half2* h2 = reinterpret_cast<const __half2*>(g_h);

    __half2 v[KNBR];
#pragma unroll
    for (int k = 0; k < KNBR; k++) {
        int idx = snb[ty * KNBR + k];                 // smem broadcast
        v[k] = __ldg(&h2[(size_t)idx * (OUT_C / 2) + tx]);
    }

    bsort16h(v);
    bsort16h(v + 16);

    // 16th smallest (rank index 15) of the merge of two sorted 16-arrays,
    // computed independently in both half lanes
    __half2 med = __hmin2(v[0], v[31]);
#pragma unroll
    for (int i = 1; i < 16; i++)
        med = __hmax2(med, __hmin2(v[i], v[31 - i]));

    float2 f = __half22float2(med);
    float2* o = reinterpret_cast<float2*>(out + (size_t)node * OUT_C) + tx;
    *o = f;
}

// ---------------------------------------------------------------------------
extern "C" void kernel_launch(void* const* d_in, const int* in_sizes, int n_in,
                              void* d_out, int out_size) {
    const float* x    = (const float*)d_in[0];
    const int*   nbrs = (const int*)d_in[1];
    const float* W    = (const float*)d_in[2];
    float*       out  = (float*)d_out;

    const int n = in_sizes[0] / IN_C;   // 100000

    // idempotent; required for 99.8KB dynamic smem
    cudaFuncSetAttribute(gemm_kernel,
                         cudaFuncAttributeMaxDynamicSharedMemorySize,
                         SMEM_BYTES);

    gemm_kernel<<<(n + BM - 1) / BM, 256, SMEM_BYTES>>>(x, W, n);
    median_kernel<<<(n + 7) / 8, 256>>>(nbrs, out, n);
}

// round 17
// speedup vs baseline: 1.0210x; 1.0210x over previous
#include <cuda_runtime.h>
#include <cuda_fp16.h>
#include <cstdint>

// ---------------------------------------------------------------------------
// MedianConvolution: out[n,c] = lower_median_k( (x @ W^T)[nbrs[n,k], c] )
// N=100000, K=32, IN_C=128, OUT_C=64.  nbrs is int32 (JAX demotes int64).
// GEMM: fp32 FFMA2 tiled (R11, measured 44.8us).  h stored fp16.
// Median: packed half2 Batcher network, 5-blocks/SM launch bound.
// ---------------------------------------------------------------------------

#define N_NODES 100000
#define IN_C    128
#define OUT_C   64
#define KNBR    32

// gemm tile config (R11)
#define BM 128
#define BK 16
#define TM 8
#define TN 4
#define XPAD 4
#define WPAD 4

// intermediate h = x @ W^T in fp16 (12.8 MB static scratch — allocation-free)
__device__ __align__(16) __half g_h[N_NODES * OUT_C];

typedef unsigned long long u64;

__device__ __forceinline__ u64 pk2(float a, float b) {
    u64 r;
    asm("mov.b64 %0, {%1, %2};" : "=l"(r) : "f"(a), "f"(b));
    return r;
}
__device__ __forceinline__ void upk2(u64 p, float& a, float& b) {
    asm("mov.b64 {%0, %1}, %2;" : "=f"(a), "=f"(b) : "l"(p));
}
__device__ __forceinline__ void fma2(u64& acc, u64 x2, u64 w2) {
    asm("fma.rn.f32x2 %0, %1, %2, %0;" : "+l"(acc) : "l"(x2), "l"(w2));
}

// ---------------------------------------------------------------------------
// Kernel 1: h = x @ W^T.  2D block-tiled, FFMA2 inner loop (R11, proven).
// ---------------------------------------------------------------------------
__global__ __launch_bounds__(256) void gemm_kernel(
    const float* __restrict__ x,
    const float* __restrict__ W,
    int n)
{
    __shared__ float wt[IN_C][OUT_C + WPAD];   // 34.8 KB
    __shared__ float xs[BK][BM + XPAD];        // 8.4 KB (row stride 528B)

    const int tid = threadIdx.x;
    const int tx = tid & 15;                // col group: cols tx*4..+3
    const int ty = tid >> 4;                // row group: rows ty*8..+7
    const int rowBase = blockIdx.x * BM;

    for (int e = tid; e < OUT_C * IN_C; e += 256) {
        int c = e >> 7, k = e & 127;
        wt[k][c] = W[e];
    }

    u64 acc2[TM / 2][TN];                   // [row-pair][col]
#pragma unroll
    for (int i = 0; i < TM / 2; i++)
#pragma unroll
        for (int j = 0; j < TN; j++) acc2[i][j] = 0ull;

    for (int kb = 0; kb < IN_C / BK; kb++) {
        __syncthreads();
#pragma unroll
        for (int i = 0; i < 2; i++) {
            int e   = tid + i * 256;
            int row = e >> 2;
            int q   = e & 3;
            int grow = rowBase + row;
            float4 v = make_float4(0.f, 0.f, 0.f, 0.f);
            if (grow < n)
                v = __ldg(reinterpret_cast<const float4*>(
                        x + (size_t)grow * IN_C + kb * BK) + q);
            xs[q * 4 + 0][row] = v.x;
            xs[q * 4 + 1][row] = v.y;
            xs[q * 4 + 2][row] = v.z;
            xs[q * 4 + 3][row] = v.w;
        }
        __syncthreads();

#pragma unroll
        for (int k = 0; k < BK; k++) {
            const ulonglong2 xA =
                *reinterpret_cast<const ulonglong2*>(&xs[k][ty * TM]);
            const ulonglong2 xB =
                *reinterpret_cast<const ulonglong2*>(&xs[k][ty * TM + 4]);
            const float4 wv =
                *reinterpret_cast<const float4*>(&wt[kb * BK + k][tx * TN]);

            const u64 xp[TM / 2] = { xA.x, xA.y, xB.x, xB.y };
            const u64 w2[TN] = { pk2(wv.x, wv.x), pk2(wv.y, wv.y),
                                 pk2(wv.z, wv.z), pk2(wv.w, wv.w) };
#pragma unroll
            for (int i = 0; i < TM / 2; i++) {
                fma2(acc2[i][0], xp[i], w2[0]);
                fma2(acc2[i][1], xp[i], w2[1]);
                fma2(acc2[i][2], xp[i], w2[2]);
                fma2(acc2[i][3], xp[i], w2[3]);
            }
        }
    }

#pragma unroll
    for (int i = 0; i < TM / 2; i++) {
        float lo[TN], hi[TN];
#pragma unroll
        for (int c = 0; c < TN; c++) upk2(acc2[i][c], lo[c], hi[c]);

        int r0 = rowBase + ty * TM + 2 * i;
        if (r0 < n) {
            __half2* o = reinterpret_cast<__half2*>(
                g_h + (size_t)r0 * OUT_C + tx * TN);
            o[0] = __floats2half2_rn(lo[0], lo[1]);
            o[1] = __floats2half2_rn(lo[2], lo[3]);
        }
        int r1 = r0 + 1;
        if (r1 < n) {
            __half2* o = reinterpret_cast<__half2*>(
                g_h + (size_t)r1 * OUT_C + tx * TN);
            o[0] = __floats2half2_rn(hi[0], hi[1]);
            o[1] = __floats2half2_rn(hi[2], hi[3]);
        }
    }
}

// ---------------------------------------------------------------------------
// Kernel 2: gather + lower-median over K=32, packed half2 (2 channels/thread).
// 256 threads/block = 8 nodes x 32 threads; warp = 32 channel-pairs of one
// node -> each neighbor gather is exactly one 128B line (L2-resident).
// Median: explicit Batcher odd-even mergesort (63 comparators) per half,
// then median = tournament-max of min(A[i], B[15-i]) (depth-4 merge).
// __launch_bounds__(256,5): cap regs ~51 -> 5 blocks/SM.
// ---------------------------------------------------------------------------
__device__ __forceinline__ void cas2(__half2& a, __half2& b) {
    __half2 lo = __hmin2(a, b);
    b = __hmax2(a, b);
    a = lo;
}

#define S(i,j) cas2(v[i], v[j])
__device__ __forceinline__ void bsort16h(__half2* v) {
    // L1
    S(0,1); S(2,3); S(4,5); S(6,7); S(8,9); S(10,11); S(12,13); S(14,15);
    // L2
    S(0,2); S(1,3); S(4,6); S(5,7); S(8,10); S(9,11); S(12,14); S(13,15);
    // L3
    S(1,2); S(5,6); S(9,10); S(13,14);
    // L4
    S(0,4); S(1,5); S(2,6); S(3,7); S(8,12); S(9,13); S(10,14); S(11,15);
    // L5
    S(2,4); S(3,5); S(10,12); S(11,13);
    // L6
    S(1,2); S(3,4); S(5,6); S(9,10); S(11,12); S(13,14);
    // L7
    S(0,8); S(1,9); S(2,10); S(3,11); S(4,12); S(5,13); S(6,14); S(7,15);
    // L8
    S(4,8); S(5,9); S(6,10); S(7,11);
    // L9
    S(2,4); S(3,5); S(6,8); S(7,9); S(10,12); S(11,13);
    // L10
    S(1,2); S(3,4); S(5,6); S(7,8); S(9,10); S(11,12); S(13,14);
}
#undef S

__global__ __launch_bounds__(256, 5) void median_kernel(
    const int* __restrict__ nbrs,      // int32
    float* __restrict__ out,
    int n)
{
    __shared__ int snb[8 * KNBR];

    const int base = blockIdx.x * 8;
    const int tid = threadIdx.x;

    {
        int node = base + (tid >> 5);
        int idx = (node < n) ? nbrs[(size_t)node * KNBR + (tid & 31)] : 0;
        idx = max(0, min(idx, n - 1));   // defensive clamp
        snb[tid] = idx;
    }
    __syncthreads();

    const int ty = tid >> 5;   // node within block (0..7)
    const int tx = tid & 31;   // channel-pair index (channels 2tx, 2tx+1)
    const int node = base + ty;
    if (node >= n) return;

    const __half2* h2 = reinterpret_cast<const __half2*>(g_h);

    __half2 v[KNBR];
#pragma unroll
    for (int k = 0; k < KNBR; k++) {
        int idx = snb[ty * KNBR + k];                 // smem broadcast
        v[k] = __ldg(&h2[(size_t)idx * (OUT_C / 2) + tx]);
    }

    bsort16h(v);
    bsort16h(v + 16);

    // 16th smallest of merge: mins m[i]=min(A[i],B[15-i]), then tournament max
    __half2 m[16];
#pragma unroll
    for (int i = 0; i < 16; i++)
        m[i] = __hmin2(v[i], v[31 - i]);
#pragma unroll
    for (int s = 8; s > 0; s >>= 1)
#pragma unroll
        for (int i = 0; i < s; i++)
            m[i] = __hmax2(m[i], m[i + s]);

    float2 f = __half22float2(m[0]);
    float2* o = reinterpret_cast<float2*>(out + (size_t)node * OUT_C) + tx;
    *o = f;
}

// ---------------------------------------------------------------------------
extern "C" void kernel_launch(void* const* d_in, const int* in_sizes, int n_in,
                              void* d_out, int out_size) {
    const float* x    = (const float*)d_in[0];
    const int*   nbrs = (const int*)d_in[1];
    const float* W    = (const float*)d_in[2];
    float*       out  = (float*)d_out;

    const int n = in_sizes[0] / IN_C;   // 100000

    gemm_kernel<<<(n + BM - 1) / BM, 256>>>(x, W, n);
    median_kernel<<<(n + 7) / 8, 256>>>(nbrs, out, n);
}